// round 14
// baseline (speedup 1.0000x reference)
#include <cuda_runtime.h>
#include <cuda_bf16.h>
#include <cstdint>

#define Bb 64
#define Nn 1024
#define Cc 768
#define NHh 12
#define KDd 64
#define MROWS (Bb * Nn)

// ---------------- scratch ---------------------------------------------------
__device__ float g_q[Bb * NHh * Nn];
__device__ float g_w[Bb * NHh * Nn];
__device__ float g_sig[Bb * NHh];
__device__ float g_tp[Bb * 8 * NHh * Cc];
__device__ float g_cv[Bb * Cc];
__device__ __align__(16) __nv_bfloat16 g_xb[(size_t)MROWS * Cc];   // x bf16
__device__ __align__(16) uint8_t g_xf8[(size_t)MROWS * Cc];        // x e4m3
__device__ __align__(16) uint8_t g_vf8[(size_t)MROWS * Cc];        // relu(v)*cv*2048 e4m3
__device__ __align__(16) uint8_t g_wvf8[Cc * Cc];                  // Wv*64 e4m3
__device__ __align__(16) uint8_t g_wof8[Cc * Cc];                  // Wout*64 e4m3
__device__ __align__(16) __nv_bfloat16 g_wqb[16 * Cc];             // Wq bf16 (rows 12-15 zero)

__device__ __forceinline__ uint32_t f2bf2(float lo, float hi) {
    uint32_t r;
    asm("cvt.rn.bf16x2.f32 %0, %1, %2;" : "=r"(r) : "f"(hi), "f"(lo));
    return r;
}
__device__ __forceinline__ uint16_t f2e4m3x2(float lo, float hi) {
    uint16_t r;
    asm("cvt.rn.satfinite.e4m3x2.f32 %0, %1, %2;" : "=h"(r) : "f"(hi), "f"(lo));
    return r;
}
__device__ __forceinline__ uint32_t smem_u32(const void* p) {
    uint32_t a;
    asm("{ .reg .u64 t; cvta.to.shared.u64 t, %1; cvt.u32.u64 %0, t; }" : "=r"(a) : "l"(p));
    return a;
}
#define CP_COMMIT() asm volatile("cp.async.commit_group;" ::: "memory")
#define CP_WAIT1() asm volatile("cp.async.wait_group 1;" ::: "memory")

__device__ __forceinline__ void ldsm4(uint32_t& r0, uint32_t& r1, uint32_t& r2,
                                      uint32_t& r3, uint32_t a) {
    asm volatile("ldmatrix.sync.aligned.m8n8.x4.shared.b16 {%0,%1,%2,%3}, [%4];"
                 : "=r"(r0), "=r"(r1), "=r"(r2), "=r"(r3) : "r"(a));
}
__device__ __forceinline__ void cp16(uint32_t s, const void* g) {
    asm volatile("cp.async.cg.shared.global [%0], [%1], 16;" :: "r"(s), "l"(g));
}
__device__ __forceinline__ void mma_bf16(float c[4], const uint32_t a[4],
                                         const uint32_t b0, const uint32_t b1) {
    asm volatile(
        "mma.sync.aligned.m16n8k16.row.col.f32.bf16.bf16.f32 "
        "{%0,%1,%2,%3}, {%4,%5,%6,%7}, {%8,%9}, {%0,%1,%2,%3};"
        : "+f"(c[0]), "+f"(c[1]), "+f"(c[2]), "+f"(c[3])
        : "r"(a[0]), "r"(a[1]), "r"(a[2]), "r"(a[3]), "r"(b0), "r"(b1));
}
__device__ __forceinline__ void mma_e4m3(float c[4], const uint32_t a[4],
                                         const uint32_t b0, const uint32_t b1) {
    asm volatile(
        "mma.sync.aligned.m16n8k32.row.col.f32.e4m3.e4m3.f32 "
        "{%0,%1,%2,%3}, {%4,%5,%6,%7}, {%8,%9}, {%0,%1,%2,%3};"
        : "+f"(c[0]), "+f"(c[1]), "+f"(c[2]), "+f"(c[3])
        : "r"(a[0]), "r"(a[1]), "r"(a[2]), "r"(a[3]), "r"(b0), "r"(b1));
}

// ---------------- k1a: x conversion + (tail blocks) weight conversion -------
__global__ void __launch_bounds__(256) k1a_conv(const float* __restrict__ x,
                                                const float* __restrict__ wqkv,
                                                const float* __restrict__ wout) {
    if (blockIdx.x >= 4096) {
        // ---- weight conversion (former k0), blocks 4096..4863 ----
        int o = blockIdx.x - 4096;
        int h = o >> 6, d = o & 63;
        const float4* s1 = (const float4*)(wqkv + (size_t)(h * 129 + 65 + d) * Cc);
        const float4* s2 = (const float4*)(wout + (size_t)o * Cc);
        uint32_t* d1 = (uint32_t*)(g_wvf8 + (size_t)o * Cc);
        uint32_t* d2 = (uint32_t*)(g_wof8 + (size_t)o * Cc);
        for (int i = threadIdx.x; i < Cc / 4; i += 256) {
            float4 a = s1[i];
            d1[i] = (uint32_t)f2e4m3x2(a.x * 64.f, a.y * 64.f) |
                    ((uint32_t)f2e4m3x2(a.z * 64.f, a.w * 64.f) << 16);
            float4 b = s2[i];
            d2[i] = (uint32_t)f2e4m3x2(b.x * 64.f, b.y * 64.f) |
                    ((uint32_t)f2e4m3x2(b.z * 64.f, b.w * 64.f) << 16);
        }
        if (o < 16) {
            uint32_t* dq = (uint32_t*)g_wqb + o * (Cc / 2);
            if (o < 12) {
                const float2* sq = (const float2*)(wqkv + (size_t)(o * 129) * Cc);
                for (int i = threadIdx.x; i < Cc / 2; i += 256) {
                    float2 v = sq[i];
                    dq[i] = f2bf2(v.x, v.y);
                }
            } else {
                for (int i = threadIdx.x; i < Cc / 2; i += 256) dq[i] = 0u;
            }
        }
        return;
    }
    // ---- x -> bf16 + e4m3 streaming ----
    const float4* x4 = (const float4*)x;
    uint2* xb2 = (uint2*)g_xb;
    uint32_t* xf1 = (uint32_t*)g_xf8;
    size_t gt = (size_t)blockIdx.x * 256 + threadIdx.x;
#pragma unroll
    for (int k = 0; k < 12; k++) {
        size_t i = gt + (size_t)k * 1048576;
        float4 v = x4[i];
        xb2[i] = make_uint2(f2bf2(v.x, v.y), f2bf2(v.z, v.w));
        xf1[i] = (uint32_t)f2e4m3x2(v.x, v.y) | ((uint32_t)f2e4m3x2(v.z, v.w) << 16);
    }
}

// ---------------- k1q: q = x_bf16 @ Wq^T via HMMA ---------------------------
#define K1Q_SMEM (24576 + 3 * 16384)
__global__ void __launch_bounds__(128, 2) k1q_gemm() {
    extern __shared__ char smem[];
    const uint32_t tb = smem_u32(smem);

    const int tid = threadIdx.x;
    const int warp = tid >> 5, lane = tid & 31;
    const int gid = lane >> 2, tg = lane & 3;
    const int seg = lane >> 3, l7 = lane & 7;
    const int row0 = blockIdx.x * 128;

    for (int idx = tid; idx < 1536; idx += 128) {
        int kc = idx >> 7;
        int rem = idx & 127;
        int n = rem >> 3, j = rem & 7;
        const char* src = (const char*)g_wqb + n * 1536 + kc * 128 + j * 16;
        cp16(tb + kc * 2048 + n * 128 + ((j ^ (n & 7)) * 16), src);
    }

    const char* gA = (const char*)g_xb + (size_t)(row0 + (tid >> 3)) * 1536 + (tid & 7) * 16;
    const uint32_t swoA = (uint32_t)((tid >> 3) * 128 + (((tid & 7) ^ ((tid >> 3) & 7)) * 16));

#define K1Q_LOAD(kc, s)                                                         \
    do {                                                                        \
        uint32_t _aT = tb + 24576 + (s) * 16384 + swoA;                         \
        const char* _ga = gA + (kc) * 128;                                      \
        asm volatile(                                                           \
            "cp.async.cg.shared.global [%0], [%1], 16;\n\t"                     \
            "cp.async.cg.shared.global [%0+2048], [%1+24576], 16;\n\t"          \
            "cp.async.cg.shared.global [%0+4096], [%1+49152], 16;\n\t"          \
            "cp.async.cg.shared.global [%0+6144], [%1+73728], 16;\n\t"          \
            "cp.async.cg.shared.global [%0+8192], [%1+98304], 16;\n\t"          \
            "cp.async.cg.shared.global [%0+10240], [%1+122880], 16;\n\t"        \
            "cp.async.cg.shared.global [%0+12288], [%1+147456], 16;\n\t"        \
            "cp.async.cg.shared.global [%0+14336], [%1+172032], 16;\n\t"        \
            :: "r"(_aT), "l"(_ga));                                             \
    } while (0)

    K1Q_LOAD(0, 0); CP_COMMIT();
    K1Q_LOAD(1, 1); CP_COMMIT();

    const uint32_t aRowOff = (uint32_t)((warp * 32 + (seg & 1) * 8 + l7) * 128);
    const uint32_t kselA = (uint32_t)(seg >> 1);
    const uint32_t bRowOff = (uint32_t)(((seg >> 1) * 8 + l7) * 128);
    const uint32_t kselB = (uint32_t)(seg & 1);

    float acc[2][2][4];
#pragma unroll
    for (int mi = 0; mi < 2; mi++)
#pragma unroll
        for (int n2 = 0; n2 < 2; n2++)
#pragma unroll
            for (int rg = 0; rg < 4; rg++) acc[mi][n2][rg] = 0.f;

#pragma unroll 1
    for (int kc = 0; kc < 12; kc++) {
        CP_WAIT1();
        __syncthreads();
        if (kc + 2 < 12) K1Q_LOAD(kc + 2, (kc + 2) % 3);
        CP_COMMIT();

        const uint32_t aT = tb + 24576 + (kc % 3) * 16384 + aRowOff;
        const uint32_t bT = tb + kc * 2048 + bRowOff;

#pragma unroll
        for (int ks = 0; ks < 4; ks++) {
            const uint32_t xa = (((uint32_t)(ks * 2) + kselA) ^ (uint32_t)l7) * 16u;
            const uint32_t xb2 = (((uint32_t)(ks * 2) + kselB) ^ (uint32_t)l7) * 16u;
            uint32_t af[2][4], bf[4];
            ldsm4(af[0][0], af[0][1], af[0][2], af[0][3], aT + xa);
            ldsm4(af[1][0], af[1][1], af[1][2], af[1][3], aT + xa + 2048);
            ldsm4(bf[0], bf[1], bf[2], bf[3], bT + xb2);
#pragma unroll
            for (int mi = 0; mi < 2; mi++) {
                mma_bf16(acc[mi][0], af[mi], bf[0], bf[1]);
                mma_bf16(acc[mi][1], af[mi], bf[2], bf[3]);
            }
        }
    }

#pragma unroll
    for (int mi = 0; mi < 2; mi++) {
#pragma unroll
        for (int n2 = 0; n2 < 2; n2++) {
#pragma unroll
            for (int rg = 0; rg < 4; rg++) {
                int row = row0 + warp * 32 + mi * 16 + gid + ((rg >> 1) ? 8 : 0);
                int h = n2 * 8 + tg * 2 + (rg & 1);
                if (h < NHh) {
                    int b = row >> 10, n = row & 1023;
                    g_q[((size_t)b * NHh + h) * Nn + n] = acc[mi][n2][rg];
                }
            }
        }
    }
}

// ---------------- K2: softmax + *w_cv + sigma -------------------------------
__global__ void __launch_bounds__(256) k2_softmax(const float* __restrict__ wcv) {
    int bh = blockIdx.x;
    int tid = threadIdx.x;
    const float* q = g_q + (size_t)bh * Nn;
    __shared__ float red[256];

    float v0[4];
    float m = -1e30f;
#pragma unroll
    for (int i = 0; i < 4; i++) { v0[i] = q[tid + 256 * i]; m = fmaxf(m, v0[i]); }
    red[tid] = m; __syncthreads();
    for (int s = 128; s; s >>= 1) { if (tid < s) red[tid] = fmaxf(red[tid], red[tid + s]); __syncthreads(); }
    m = red[0]; __syncthreads();

    float e[4]; float sum = 0.f;
#pragma unroll
    for (int i = 0; i < 4; i++) { e[i] = expf(v0[i] - m); sum += e[i]; }
    red[tid] = sum; __syncthreads();
    for (int s = 128; s; s >>= 1) { if (tid < s) red[tid] += red[tid + s]; __syncthreads(); }
    float inv = 1.f / red[0]; __syncthreads();

    float wsum = 0.f;
#pragma unroll
    for (int i = 0; i < 4; i++) {
        int n = tid + 256 * i;
        float wv = e[i] * inv * wcv[n];
        g_w[(size_t)bh * Nn + n] = wv;
        wsum += wv;
    }
    red[tid] = wsum; __syncthreads();
    for (int s = 128; s; s >>= 1) { if (tid < s) red[tid] += red[tid + s]; __syncthreads(); }
    if (tid == 0) g_sig[bh] = red[0];
}

// ---------------- K3: t partials; transposed weights, float4 LDS ------------
__global__ void __launch_bounds__(128) k3_t() {
    int b = blockIdx.y;
    int ch = blockIdx.z;
    int cp = blockIdx.x * 128 + threadIdx.x;
    __shared__ __align__(16) float sw[128 * 12];   // [n][h], h-fastest
    for (int idx = threadIdx.x; idx < NHh * 128; idx += 128) {
        int h = idx >> 7, n = idx & 127;
        sw[n * 12 + h] = g_w[((size_t)b * NHh + h) * Nn + ch * 128 + n];
    }
    __syncthreads();

    float acc0[NHh], acc1[NHh];
#pragma unroll
    for (int h = 0; h < NHh; h++) { acc0[h] = 0.f; acc1[h] = 0.f; }
    const uint32_t* xb = (const uint32_t*)g_xb + ((size_t)b * Nn + ch * 128) * (Cc / 2) + cp;
#pragma unroll 2
    for (int n = 0; n < 128; n++) {
        uint32_t u = xb[(size_t)n * (Cc / 2)];
        float lo = __uint_as_float(u << 16);
        float hi = __uint_as_float(u & 0xffff0000u);
        const float4* swr = (const float4*)(sw + n * 12);
        float4 w0 = swr[0], w1 = swr[1], w2 = swr[2];
        acc0[0] += lo * w0.x;  acc1[0] += hi * w0.x;
        acc0[1] += lo * w0.y;  acc1[1] += hi * w0.y;
        acc0[2] += lo * w0.z;  acc1[2] += hi * w0.z;
        acc0[3] += lo * w0.w;  acc1[3] += hi * w0.w;
        acc0[4] += lo * w1.x;  acc1[4] += hi * w1.x;
        acc0[5] += lo * w1.y;  acc1[5] += hi * w1.y;
        acc0[6] += lo * w1.z;  acc1[6] += hi * w1.z;
        acc0[7] += lo * w1.w;  acc1[7] += hi * w1.w;
        acc0[8] += lo * w2.x;  acc1[8] += hi * w2.x;
        acc0[9] += lo * w2.y;  acc1[9] += hi * w2.y;
        acc0[10] += lo * w2.z; acc1[10] += hi * w2.z;
        acc0[11] += lo * w2.w; acc1[11] += hi * w2.w;
    }
    float* tp = g_tp + ((size_t)(b * 8 + ch) * NHh) * Cc;
#pragma unroll
    for (int h = 0; h < NHh; h++) {
        tp[h * Cc + 2 * cp] = acc0[h];
        tp[h * Cc + 2 * cp + 1] = acc1[h];
    }
}

// ---------------- K4: cv ----------------------------------------------------
__global__ void __launch_bounds__(256) k4_cv(const float* __restrict__ wqkv,
                                             const float* __restrict__ bqkv) {
    int b = blockIdx.x;
    __shared__ float st[NHh * Cc];
    for (int i = threadIdx.x; i < NHh * Cc; i += 256) {
        float s = 0.f;
#pragma unroll
        for (int ch = 0; ch < 8; ch++)
            s += g_tp[((size_t)(b * 8 + ch) * NHh) * Cc + i];
        st[i] = s;
    }
    __syncthreads();

    int tid = threadIdx.x;
    int i0 = tid, i1 = tid + 256, i2 = tid + 512;
    int h0 = i0 >> 6, d0 = i0 & 63;
    int h1 = i1 >> 6, d1 = i1 & 63;
    int h2 = i2 >> 6, d2 = i2 & 63;
    const float4* w0 = (const float4*)(wqkv + (size_t)(h0 * 129 + 1 + d0) * Cc);
    const float4* w1 = (const float4*)(wqkv + (size_t)(h1 * 129 + 1 + d1) * Cc);
    const float4* w2 = (const float4*)(wqkv + (size_t)(h2 * 129 + 1 + d2) * Cc);
    const float4* t0 = (const float4*)(st + h0 * Cc);
    const float4* t1 = (const float4*)(st + h1 * Cc);
    const float4* t2 = (const float4*)(st + h2 * Cc);
    float a0 = 0.f, a1 = 0.f, a2 = 0.f;
#pragma unroll 4
    for (int i = 0; i < Cc / 4; i++) {
        float4 wa = w0[i], ta = t0[i];
        a0 += wa.x * ta.x + wa.y * ta.y + wa.z * ta.z + wa.w * ta.w;
        float4 wb = w1[i], tb = t1[i];
        a1 += wb.x * tb.x + wb.y * tb.y + wb.z * tb.z + wb.w * tb.w;
        float4 wc = w2[i], tc = t2[i];
        a2 += wc.x * tc.x + wc.y * tc.y + wc.z * tc.z + wc.w * tc.w;
    }
    g_cv[b * Cc + i0] = a0 + bqkv[h0 * 129 + 1 + d0] * g_sig[b * NHh + h0];
    g_cv[b * Cc + i1] = a1 + bqkv[h1 * 129 + 1 + d1] * g_sig[b * NHh + h1];
    g_cv[b * Cc + i2] = a2 + bqkv[h2 * 129 + 1 + d2] * g_sig[b * NHh + h2];
}

// ---------------- fp8 GEMM: 128x64 tile, 3-stage, fragment double-buffering -
#define K5_STAGES 3
#define K5_STAGE_BYTES 24576
#define K5_SMEM (K5_STAGES * K5_STAGE_BYTES)

#define K5F_LOAD(gA, gB, kc, s)                                                 \
    do {                                                                        \
        uint32_t _aT = tb + (s) * K5_STAGE_BYTES + swo0;                        \
        uint32_t _bT = _aT + 16384;                                             \
        const char* _ga = (gA) + (kc) * 128;                                    \
        const char* _gb = (gB) + (kc) * 128;                                    \
        asm volatile(                                                           \
            "cp.async.cg.shared.global [%0], [%2], 16;\n\t"                     \
            "cp.async.cg.shared.global [%0+2048], [%2+12288], 16;\n\t"          \
            "cp.async.cg.shared.global [%0+4096], [%2+24576], 16;\n\t"          \
            "cp.async.cg.shared.global [%0+6144], [%2+36864], 16;\n\t"          \
            "cp.async.cg.shared.global [%0+8192], [%2+49152], 16;\n\t"          \
            "cp.async.cg.shared.global [%0+10240], [%2+61440], 16;\n\t"         \
            "cp.async.cg.shared.global [%0+12288], [%2+73728], 16;\n\t"         \
            "cp.async.cg.shared.global [%0+14336], [%2+86016], 16;\n\t"         \
            "cp.async.cg.shared.global [%1], [%3], 16;\n\t"                     \
            "cp.async.cg.shared.global [%1+2048], [%3+12288], 16;\n\t"          \
            "cp.async.cg.shared.global [%1+4096], [%3+24576], 16;\n\t"          \
            "cp.async.cg.shared.global [%1+6144], [%3+36864], 16;\n\t"          \
            :: "r"(_aT), "r"(_bT), "l"(_ga), "l"(_gb));                         \
    } while (0)

#define K5F_LDSM(buf, ks)                                                       \
    do {                                                                        \
        const uint32_t _xa = (((uint32_t)((ks) * 2) + kselA) ^ (uint32_t)l7) * 16u; \
        const uint32_t _xb = (((uint32_t)((ks) * 2) + kselB) ^ (uint32_t)l7) * 16u; \
        const uint32_t _a0 = aT + _xa;                                          \
        ldsm4(af[buf][0][0], af[buf][0][1], af[buf][0][2], af[buf][0][3], _a0); \
        ldsm4(af[buf][1][0], af[buf][1][1], af[buf][1][2], af[buf][1][3], _a0 + 2048); \
        const uint32_t _b0 = bT + _xb;                                          \
        ldsm4(bf[buf][0][0], bf[buf][0][1], bf[buf][0][2], bf[buf][0][3], _b0); \
        ldsm4(bf[buf][1][0], bf[buf][1][1], bf[buf][1][2], bf[buf][1][3], _b0 + 2048); \
        ldsm4(bf[buf][2][0], bf[buf][2][1], bf[buf][2][2], bf[buf][2][3], _b0 + 4096); \
        ldsm4(bf[buf][3][0], bf[buf][3][1], bf[buf][3][2], bf[buf][3][3], _b0 + 6144); \
    } while (0)

#define K5F_MAINLOOP(gA, gB)                                                    \
    K5F_LOAD(gA, gB, 0, 0); CP_COMMIT();                                        \
    K5F_LOAD(gA, gB, 1, 1); CP_COMMIT();                                        \
    _Pragma("unroll 1")                                                         \
    for (int kc = 0; kc < 6; kc++) {                                            \
        CP_WAIT1();                                                             \
        __syncthreads();                                                        \
        if (kc + 2 < 6) K5F_LOAD(gA, gB, kc + 2, (kc + 2) % K5_STAGES);         \
        CP_COMMIT();                                                            \
        const uint32_t stBase = tb + (kc % K5_STAGES) * K5_STAGE_BYTES;         \
        const uint32_t aT = stBase + aRowOff;                                   \
        const uint32_t bT = stBase + 16384 + bRowOff;                           \
        uint32_t af[2][2][4];                                                   \
        uint32_t bf[2][4][4];                                                   \
        K5F_LDSM(0, 0);                                                         \
        _Pragma("unroll")                                                       \
        for (int ks = 0; ks < 4; ks++) {                                        \
            const int cur = ks & 1;                                             \
            if (ks < 3) { K5F_LDSM((ks + 1) & 1, ks + 1); }                     \
            _Pragma("unroll")                                                   \
            for (int mi = 0; mi < 2; mi++) {                                    \
                _Pragma("unroll")                                               \
                for (int n2 = 0; n2 < 4; n2++) {                                \
                    mma_e4m3(acc[mi][2 * n2], af[cur][mi], bf[cur][n2][0], bf[cur][n2][1]); \
                    mma_e4m3(acc[mi][2 * n2 + 1], af[cur][mi], bf[cur][n2][2], bf[cur][n2][3]); \
                }                                                               \
            }                                                                   \
        }                                                                       \
    }

#define K5F_PROLOG                                                              \
    extern __shared__ char smem[];                                              \
    const uint32_t tb = smem_u32(smem);                                         \
    const int tid = threadIdx.x;                                                \
    const int warp = tid >> 5, lane = tid & 31;                                 \
    const int gid = lane >> 2, tg = lane & 3;                                   \
    const int seg = lane >> 3, l7 = lane & 7;                                   \
    const int arow0 = blockIdx.y * 128;                                         \
    const int brow0 = blockIdx.x * 64;                                          \
    const uint32_t swo0 = (uint32_t)((tid >> 3) * 128 + (((tid & 7) ^ ((tid >> 3) & 7)) * 16)); \
    const uint32_t aRowOff = (uint32_t)((warp * 32 + (seg & 1) * 8 + l7) * 128); \
    const uint32_t bRowOff = (uint32_t)(((seg >> 1) * 8 + l7) * 128);           \
    const uint32_t kselA = (uint32_t)(seg >> 1);                                \
    const uint32_t kselB = (uint32_t)(seg & 1);                                 \
    float acc[2][8][4];                                                         \
    _Pragma("unroll")                                                           \
    for (int mi = 0; mi < 2; mi++)                                              \
        _Pragma("unroll")                                                       \
        for (int ni = 0; ni < 8; ni++)                                          \
            _Pragma("unroll")                                                   \
            for (int rg = 0; rg < 4; rg++) acc[mi][ni][rg] = 0.f;

// ---------------- G1: x @ Wv^T, epilogue relu(acc/64+bv)*cv*2048 -> fp8 ------
__global__ void __launch_bounds__(128, 3) g1_gemm(const float* __restrict__ bias) {
    K5F_PROLOG
    const char* gA = (const char*)g_xf8 + (size_t)(arow0 + (tid >> 3)) * Cc + (tid & 7) * 16;
    const char* gB = (const char*)g_wvf8 + (size_t)(brow0 + (tid >> 3)) * Cc + (tid & 7) * 16;
    K5F_MAINLOOP(gA, gB)

    const float inv64 = 1.f / 64.f;
    const float s2048 = 2048.f;
#pragma unroll
    for (int mi = 0; mi < 2; mi++) {
        int row = arow0 + warp * 32 + mi * 16 + gid;
#pragma unroll
        for (int ni = 0; ni < 8; ni++) {
            int col = brow0 + ni * 8 + tg * 2;
            int hb = (col >> 6) * 129 + 65 + (col & 63);
            float bv0 = bias[hb], bv1 = bias[hb + 1];
            int b = row >> 10;
            float cv0 = g_cv[b * Cc + col], cv1 = g_cv[b * Cc + col + 1];
            float v00 = fmaxf(acc[mi][ni][0] * inv64 + bv0, 0.f) * cv0 * s2048;
            float v01 = fmaxf(acc[mi][ni][1] * inv64 + bv1, 0.f) * cv1 * s2048;
            float v10 = fmaxf(acc[mi][ni][2] * inv64 + bv0, 0.f) * cv0 * s2048;
            float v11 = fmaxf(acc[mi][ni][3] * inv64 + bv1, 0.f) * cv1 * s2048;
            uint16_t* dst = (uint16_t*)g_vf8;
            dst[(size_t)row * (Cc / 2) + col / 2] = f2e4m3x2(v00, v01);
            dst[(size_t)(row + 8) * (Cc / 2) + col / 2] = f2e4m3x2(v10, v11);
        }
    }
}

// ---------------- G2: vf8 @ Wout^T, epilogue acc/(2048*64)+bout -> fp32 -----
__global__ void __launch_bounds__(128, 3) g2_gemm(const float* __restrict__ bias,
                                                  float* __restrict__ outg) {
    K5F_PROLOG
    const char* gA = (const char*)g_vf8 + (size_t)(arow0 + (tid >> 3)) * Cc + (tid & 7) * 16;
    const char* gB = (const char*)g_wof8 + (size_t)(brow0 + (tid >> 3)) * Cc + (tid & 7) * 16;
    K5F_MAINLOOP(gA, gB)

    const float invS = 1.f / (2048.f * 64.f);
#pragma unroll
    for (int mi = 0; mi < 2; mi++) {
        int row = arow0 + warp * 32 + mi * 16 + gid;
#pragma unroll
        for (int ni = 0; ni < 8; ni++) {
            int col = brow0 + ni * 8 + tg * 2;
            float b0 = bias[col], b1 = bias[col + 1];
            *(float2*)(outg + (size_t)row * Cc + col) =
                make_float2(acc[mi][ni][0] * invS + b0, acc[mi][ni][1] * invS + b1);
            *(float2*)(outg + (size_t)(row + 8) * Cc + col) =
                make_float2(acc[mi][ni][2] * invS + b0, acc[mi][ni][3] * invS + b1);
        }
    }
}

// ---------------- launch ----------------------------------------------------
extern "C" void kernel_launch(void* const* d_in, const int* in_sizes, int n_in,
                              void* d_out, int out_size) {
    const float* x = (const float*)d_in[0];
    const float* wqkv = (const float*)d_in[1];
    const float* bqkv = (const float*)d_in[2];
    const float* wcv = (const float*)d_in[3];
    const float* wout = (const float*)d_in[4];
    const float* bout = (const float*)d_in[5];
    float* out = (float*)d_out;

    cudaFuncSetAttribute(k1q_gemm, cudaFuncAttributeMaxDynamicSharedMemorySize, K1Q_SMEM);
    cudaFuncSetAttribute(g1_gemm, cudaFuncAttributeMaxDynamicSharedMemorySize, K5_SMEM);
    cudaFuncSetAttribute(g2_gemm, cudaFuncAttributeMaxDynamicSharedMemorySize, K5_SMEM);

    k1a_conv<<<4096 + Cc, 256>>>(x, wqkv, wout);         // 1 (x conv + weight conv)
    k1q_gemm<<<512, 128, K1Q_SMEM>>>();                  // 2
    k2_softmax<<<Bb * NHh, 256>>>(wcv);                  // 3
    k3_t<<<dim3(3, Bb, 8), 128>>>();                     // 4  <- profiled slot
    k4_cv<<<Bb, 256>>>(wqkv, bqkv);                      // 5
    g1_gemm<<<dim3(12, 512), 128, K5_SMEM>>>(bqkv);      // 6
    g2_gemm<<<dim3(12, 512), 128, K5_SMEM>>>(bout, out); // 7
}

// round 15
// speedup vs baseline: 1.0202x; 1.0202x over previous
#include <cuda_runtime.h>
#include <cuda_bf16.h>
#include <cstdint>

#define Bb 64
#define Nn 1024
#define Cc 768
#define NHh 12
#define KDd 64
#define MROWS (Bb * Nn)

// ---------------- scratch ---------------------------------------------------
__device__ float g_q[Bb * NHh * Nn];
__device__ float g_w[Bb * NHh * Nn];
__device__ float g_sig[Bb * NHh];
__device__ float g_tp[Bb * 8 * NHh * Cc];
__device__ float g_cv[Bb * Cc];
__device__ __align__(16) __nv_bfloat16 g_xb[(size_t)MROWS * Cc];   // x bf16
__device__ __align__(16) uint8_t g_xf8[(size_t)MROWS * Cc];        // x e4m3
__device__ __align__(16) uint8_t g_vf8[(size_t)MROWS * Cc];        // relu(v)*cv*2048 e4m3
__device__ __align__(16) uint8_t g_wvf8[Cc * Cc];                  // Wv*64 e4m3
__device__ __align__(16) uint8_t g_wof8[Cc * Cc];                  // Wout*64 e4m3
__device__ __align__(16) __nv_bfloat16 g_wqb[16 * Cc];             // Wq bf16 (rows 12-15 zero)

__device__ __forceinline__ uint32_t f2bf2(float lo, float hi) {
    uint32_t r;
    asm("cvt.rn.bf16x2.f32 %0, %1, %2;" : "=r"(r) : "f"(hi), "f"(lo));
    return r;
}
__device__ __forceinline__ uint16_t f2e4m3x2(float lo, float hi) {
    uint16_t r;
    asm("cvt.rn.satfinite.e4m3x2.f32 %0, %1, %2;" : "=h"(r) : "f"(hi), "f"(lo));
    return r;
}
__device__ __forceinline__ uint32_t smem_u32(const void* p) {
    uint32_t a;
    asm("{ .reg .u64 t; cvta.to.shared.u64 t, %1; cvt.u32.u64 %0, t; }" : "=r"(a) : "l"(p));
    return a;
}
#define CP_COMMIT() asm volatile("cp.async.commit_group;" ::: "memory")
#define CP_WAIT1() asm volatile("cp.async.wait_group 1;" ::: "memory")

__device__ __forceinline__ void ldsm4(uint32_t& r0, uint32_t& r1, uint32_t& r2,
                                      uint32_t& r3, uint32_t a) {
    asm volatile("ldmatrix.sync.aligned.m8n8.x4.shared.b16 {%0,%1,%2,%3}, [%4];"
                 : "=r"(r0), "=r"(r1), "=r"(r2), "=r"(r3) : "r"(a));
}
__device__ __forceinline__ void cp16(uint32_t s, const void* g) {
    asm volatile("cp.async.cg.shared.global [%0], [%1], 16;" :: "r"(s), "l"(g));
}
__device__ __forceinline__ void mma_bf16(float c[4], const uint32_t a[4],
                                         const uint32_t b0, const uint32_t b1) {
    asm volatile(
        "mma.sync.aligned.m16n8k16.row.col.f32.bf16.bf16.f32 "
        "{%0,%1,%2,%3}, {%4,%5,%6,%7}, {%8,%9}, {%0,%1,%2,%3};"
        : "+f"(c[0]), "+f"(c[1]), "+f"(c[2]), "+f"(c[3])
        : "r"(a[0]), "r"(a[1]), "r"(a[2]), "r"(a[3]), "r"(b0), "r"(b1));
}
__device__ __forceinline__ void mma_e4m3(float c[4], const uint32_t a[4],
                                         const uint32_t b0, const uint32_t b1) {
    asm volatile(
        "mma.sync.aligned.m16n8k32.row.col.f32.e4m3.e4m3.f32 "
        "{%0,%1,%2,%3}, {%4,%5,%6,%7}, {%8,%9}, {%0,%1,%2,%3};"
        : "+f"(c[0]), "+f"(c[1]), "+f"(c[2]), "+f"(c[3])
        : "r"(a[0]), "r"(a[1]), "r"(a[2]), "r"(a[3]), "r"(b0), "r"(b1));
}

// ---------------- k1a: x conversion + (tail blocks) weight conversion -------
__global__ void __launch_bounds__(256) k1a_conv(const float* __restrict__ x,
                                                const float* __restrict__ wqkv,
                                                const float* __restrict__ wout) {
    if (blockIdx.x >= 4096) {
        int o = blockIdx.x - 4096;
        int h = o >> 6, d = o & 63;
        const float4* s1 = (const float4*)(wqkv + (size_t)(h * 129 + 65 + d) * Cc);
        const float4* s2 = (const float4*)(wout + (size_t)o * Cc);
        uint32_t* d1 = (uint32_t*)(g_wvf8 + (size_t)o * Cc);
        uint32_t* d2 = (uint32_t*)(g_wof8 + (size_t)o * Cc);
        for (int i = threadIdx.x; i < Cc / 4; i += 256) {
            float4 a = s1[i];
            d1[i] = (uint32_t)f2e4m3x2(a.x * 64.f, a.y * 64.f) |
                    ((uint32_t)f2e4m3x2(a.z * 64.f, a.w * 64.f) << 16);
            float4 b = s2[i];
            d2[i] = (uint32_t)f2e4m3x2(b.x * 64.f, b.y * 64.f) |
                    ((uint32_t)f2e4m3x2(b.z * 64.f, b.w * 64.f) << 16);
        }
        if (o < 16) {
            uint32_t* dq = (uint32_t*)g_wqb + o * (Cc / 2);
            if (o < 12) {
                const float2* sq = (const float2*)(wqkv + (size_t)(o * 129) * Cc);
                for (int i = threadIdx.x; i < Cc / 2; i += 256) {
                    float2 v = sq[i];
                    dq[i] = f2bf2(v.x, v.y);
                }
            } else {
                for (int i = threadIdx.x; i < Cc / 2; i += 256) dq[i] = 0u;
            }
        }
        return;
    }
    const float4* x4 = (const float4*)x;
    uint2* xb2 = (uint2*)g_xb;
    uint32_t* xf1 = (uint32_t*)g_xf8;
    size_t gt = (size_t)blockIdx.x * 256 + threadIdx.x;
#pragma unroll
    for (int k = 0; k < 12; k++) {
        size_t i = gt + (size_t)k * 1048576;
        float4 v = x4[i];
        xb2[i] = make_uint2(f2bf2(v.x, v.y), f2bf2(v.z, v.w));
        xf1[i] = (uint32_t)f2e4m3x2(v.x, v.y) | ((uint32_t)f2e4m3x2(v.z, v.w) << 16);
    }
}

// ---------------- k1q: q = x_bf16 @ Wq^T via HMMA ---------------------------
#define K1Q_SMEM (24576 + 3 * 16384)
__global__ void __launch_bounds__(128, 2) k1q_gemm() {
    extern __shared__ char smem[];
    const uint32_t tb = smem_u32(smem);

    const int tid = threadIdx.x;
    const int warp = tid >> 5, lane = tid & 31;
    const int gid = lane >> 2, tg = lane & 3;
    const int seg = lane >> 3, l7 = lane & 7;
    const int row0 = blockIdx.x * 128;

    for (int idx = tid; idx < 1536; idx += 128) {
        int kc = idx >> 7;
        int rem = idx & 127;
        int n = rem >> 3, j = rem & 7;
        const char* src = (const char*)g_wqb + n * 1536 + kc * 128 + j * 16;
        cp16(tb + kc * 2048 + n * 128 + ((j ^ (n & 7)) * 16), src);
    }

    const char* gA = (const char*)g_xb + (size_t)(row0 + (tid >> 3)) * 1536 + (tid & 7) * 16;
    const uint32_t swoA = (uint32_t)((tid >> 3) * 128 + (((tid & 7) ^ ((tid >> 3) & 7)) * 16));

#define K1Q_LOAD(kc, s)                                                         \
    do {                                                                        \
        uint32_t _aT = tb + 24576 + (s) * 16384 + swoA;                         \
        const char* _ga = gA + (kc) * 128;                                      \
        asm volatile(                                                           \
            "cp.async.cg.shared.global [%0], [%1], 16;\n\t"                     \
            "cp.async.cg.shared.global [%0+2048], [%1+24576], 16;\n\t"          \
            "cp.async.cg.shared.global [%0+4096], [%1+49152], 16;\n\t"          \
            "cp.async.cg.shared.global [%0+6144], [%1+73728], 16;\n\t"          \
            "cp.async.cg.shared.global [%0+8192], [%1+98304], 16;\n\t"          \
            "cp.async.cg.shared.global [%0+10240], [%1+122880], 16;\n\t"        \
            "cp.async.cg.shared.global [%0+12288], [%1+147456], 16;\n\t"        \
            "cp.async.cg.shared.global [%0+14336], [%1+172032], 16;\n\t"        \
            :: "r"(_aT), "l"(_ga));                                             \
    } while (0)

    K1Q_LOAD(0, 0); CP_COMMIT();
    K1Q_LOAD(1, 1); CP_COMMIT();

    const uint32_t aRowOff = (uint32_t)((warp * 32 + (seg & 1) * 8 + l7) * 128);
    const uint32_t kselA = (uint32_t)(seg >> 1);
    const uint32_t bRowOff = (uint32_t)(((seg >> 1) * 8 + l7) * 128);
    const uint32_t kselB = (uint32_t)(seg & 1);

    float acc[2][2][4];
#pragma unroll
    for (int mi = 0; mi < 2; mi++)
#pragma unroll
        for (int n2 = 0; n2 < 2; n2++)
#pragma unroll
            for (int rg = 0; rg < 4; rg++) acc[mi][n2][rg] = 0.f;

#pragma unroll 1
    for (int kc = 0; kc < 12; kc++) {
        CP_WAIT1();
        __syncthreads();
        if (kc + 2 < 12) K1Q_LOAD(kc + 2, (kc + 2) % 3);
        CP_COMMIT();

        const uint32_t aT = tb + 24576 + (kc % 3) * 16384 + aRowOff;
        const uint32_t bT = tb + kc * 2048 + bRowOff;

#pragma unroll
        for (int ks = 0; ks < 4; ks++) {
            const uint32_t xa = (((uint32_t)(ks * 2) + kselA) ^ (uint32_t)l7) * 16u;
            const uint32_t xb2 = (((uint32_t)(ks * 2) + kselB) ^ (uint32_t)l7) * 16u;
            uint32_t af[2][4], bf[4];
            ldsm4(af[0][0], af[0][1], af[0][2], af[0][3], aT + xa);
            ldsm4(af[1][0], af[1][1], af[1][2], af[1][3], aT + xa + 2048);
            ldsm4(bf[0], bf[1], bf[2], bf[3], bT + xb2);
#pragma unroll
            for (int mi = 0; mi < 2; mi++) {
                mma_bf16(acc[mi][0], af[mi], bf[0], bf[1]);
                mma_bf16(acc[mi][1], af[mi], bf[2], bf[3]);
            }
        }
    }

#pragma unroll
    for (int mi = 0; mi < 2; mi++) {
#pragma unroll
        for (int n2 = 0; n2 < 2; n2++) {
#pragma unroll
            for (int rg = 0; rg < 4; rg++) {
                int row = row0 + warp * 32 + mi * 16 + gid + ((rg >> 1) ? 8 : 0);
                int h = n2 * 8 + tg * 2 + (rg & 1);
                if (h < NHh) {
                    int b = row >> 10, n = row & 1023;
                    g_q[((size_t)b * NHh + h) * Nn + n] = acc[mi][n2][rg];
                }
            }
        }
    }
}

// ---------------- K2: softmax + *w_cv + sigma -------------------------------
__global__ void __launch_bounds__(256) k2_softmax(const float* __restrict__ wcv) {
    int bh = blockIdx.x;
    int tid = threadIdx.x;
    const float* q = g_q + (size_t)bh * Nn;
    __shared__ float red[256];

    float v0[4];
    float m = -1e30f;
#pragma unroll
    for (int i = 0; i < 4; i++) { v0[i] = q[tid + 256 * i]; m = fmaxf(m, v0[i]); }
    red[tid] = m; __syncthreads();
    for (int s = 128; s; s >>= 1) { if (tid < s) red[tid] = fmaxf(red[tid], red[tid + s]); __syncthreads(); }
    m = red[0]; __syncthreads();

    float e[4]; float sum = 0.f;
#pragma unroll
    for (int i = 0; i < 4; i++) { e[i] = expf(v0[i] - m); sum += e[i]; }
    red[tid] = sum; __syncthreads();
    for (int s = 128; s; s >>= 1) { if (tid < s) red[tid] += red[tid + s]; __syncthreads(); }
    float inv = 1.f / red[0]; __syncthreads();

    float wsum = 0.f;
#pragma unroll
    for (int i = 0; i < 4; i++) {
        int n = tid + 256 * i;
        float wv = e[i] * inv * wcv[n];
        g_w[(size_t)bh * Nn + n] = wv;
        wsum += wv;
    }
    red[tid] = wsum; __syncthreads();
    for (int s = 128; s; s >>= 1) { if (tid < s) red[tid] += red[tid + s]; __syncthreads(); }
    if (tid == 0) g_sig[bh] = red[0];
}

// ---------------- K3: t partials over 8 n-chunks (validated R9 form) --------
__global__ void __launch_bounds__(128) k3_t() {
    int b = blockIdx.y;
    int ch = blockIdx.z;
    int cp = blockIdx.x * 128 + threadIdx.x;
    __shared__ float sw[NHh * 128];
    for (int h = 0; h < NHh; h++)
        sw[h * 128 + threadIdx.x] = g_w[((size_t)b * NHh + h) * Nn + ch * 128 + threadIdx.x];
    __syncthreads();

    float acc0[NHh], acc1[NHh];
#pragma unroll
    for (int h = 0; h < NHh; h++) { acc0[h] = 0.f; acc1[h] = 0.f; }
    const uint32_t* xb = (const uint32_t*)g_xb + ((size_t)b * Nn + ch * 128) * (Cc / 2) + cp;
#pragma unroll 4
    for (int n = 0; n < 128; n++) {
        uint32_t u = xb[(size_t)n * (Cc / 2)];
        float lo = __uint_as_float(u << 16);
        float hi = __uint_as_float(u & 0xffff0000u);
#pragma unroll
        for (int h = 0; h < NHh; h++) {
            float wv = sw[h * 128 + n];
            acc0[h] += lo * wv;
            acc1[h] += hi * wv;
        }
    }
    float* tp = g_tp + ((size_t)(b * 8 + ch) * NHh) * Cc;
#pragma unroll
    for (int h = 0; h < NHh; h++) {
        tp[h * Cc + 2 * cp] = acc0[h];
        tp[h * Cc + 2 * cp + 1] = acc1[h];
    }
}

// ---------------- K4: cv ----------------------------------------------------
__global__ void __launch_bounds__(256) k4_cv(const float* __restrict__ wqkv,
                                             const float* __restrict__ bqkv) {
    int b = blockIdx.x;
    __shared__ float st[NHh * Cc];
    for (int i = threadIdx.x; i < NHh * Cc; i += 256) {
        float s = 0.f;
#pragma unroll
        for (int ch = 0; ch < 8; ch++)
            s += g_tp[((size_t)(b * 8 + ch) * NHh) * Cc + i];
        st[i] = s;
    }
    __syncthreads();

    int tid = threadIdx.x;
    int i0 = tid, i1 = tid + 256, i2 = tid + 512;
    int h0 = i0 >> 6, d0 = i0 & 63;
    int h1 = i1 >> 6, d1 = i1 & 63;
    int h2 = i2 >> 6, d2 = i2 & 63;
    const float4* w0 = (const float4*)(wqkv + (size_t)(h0 * 129 + 1 + d0) * Cc);
    const float4* w1 = (const float4*)(wqkv + (size_t)(h1 * 129 + 1 + d1) * Cc);
    const float4* w2 = (const float4*)(wqkv + (size_t)(h2 * 129 + 1 + d2) * Cc);
    const float4* t0 = (const float4*)(st + h0 * Cc);
    const float4* t1 = (const float4*)(st + h1 * Cc);
    const float4* t2 = (const float4*)(st + h2 * Cc);
    float a0 = 0.f, a1 = 0.f, a2 = 0.f;
#pragma unroll 4
    for (int i = 0; i < Cc / 4; i++) {
        float4 wa = w0[i], ta = t0[i];
        a0 += wa.x * ta.x + wa.y * ta.y + wa.z * ta.z + wa.w * ta.w;
        float4 wb = w1[i], tb = t1[i];
        a1 += wb.x * tb.x + wb.y * tb.y + wb.z * tb.z + wb.w * tb.w;
        float4 wc = w2[i], tc = t2[i];
        a2 += wc.x * tc.x + wc.y * tc.y + wc.z * tc.z + wc.w * tc.w;
    }
    g_cv[b * Cc + i0] = a0 + bqkv[h0 * 129 + 1 + d0] * g_sig[b * NHh + h0];
    g_cv[b * Cc + i1] = a1 + bqkv[h1 * 129 + 1 + d1] * g_sig[b * NHh + h1];
    g_cv[b * Cc + i2] = a2 + bqkv[h2 * 129 + 1 + d2] * g_sig[b * NHh + h2];
}

// ---------------- fp8 GEMM: 128x64 tile, 3-stage, fragment double-buffering -
#define K5_STAGES 3
#define K5_STAGE_BYTES 24576
#define K5_SMEM (K5_STAGES * K5_STAGE_BYTES)

#define K5F_LOAD(gA, gB, kc, s)                                                 \
    do {                                                                        \
        uint32_t _aT = tb + (s) * K5_STAGE_BYTES + swo0;                        \
        uint32_t _bT = _aT + 16384;                                             \
        const char* _ga = (gA) + (kc) * 128;                                    \
        const char* _gb = (gB) + (kc) * 128;                                    \
        asm volatile(                                                           \
            "cp.async.cg.shared.global [%0], [%2], 16;\n\t"                     \
            "cp.async.cg.shared.global [%0+2048], [%2+12288], 16;\n\t"          \
            "cp.async.cg.shared.global [%0+4096], [%2+24576], 16;\n\t"          \
            "cp.async.cg.shared.global [%0+6144], [%2+36864], 16;\n\t"          \
            "cp.async.cg.shared.global [%0+8192], [%2+49152], 16;\n\t"          \
            "cp.async.cg.shared.global [%0+10240], [%2+61440], 16;\n\t"         \
            "cp.async.cg.shared.global [%0+12288], [%2+73728], 16;\n\t"         \
            "cp.async.cg.shared.global [%0+14336], [%2+86016], 16;\n\t"         \
            "cp.async.cg.shared.global [%1], [%3], 16;\n\t"                     \
            "cp.async.cg.shared.global [%1+2048], [%3+12288], 16;\n\t"          \
            "cp.async.cg.shared.global [%1+4096], [%3+24576], 16;\n\t"          \
            "cp.async.cg.shared.global [%1+6144], [%3+36864], 16;\n\t"          \
            :: "r"(_aT), "r"(_bT), "l"(_ga), "l"(_gb));                         \
    } while (0)

#define K5F_LDSM(buf, ks)                                                       \
    do {                                                                        \
        const uint32_t _xa = (((uint32_t)((ks) * 2) + kselA) ^ (uint32_t)l7) * 16u; \
        const uint32_t _xb = (((uint32_t)((ks) * 2) + kselB) ^ (uint32_t)l7) * 16u; \
        const uint32_t _a0 = aT + _xa;                                          \
        ldsm4(af[buf][0][0], af[buf][0][1], af[buf][0][2], af[buf][0][3], _a0); \
        ldsm4(af[buf][1][0], af[buf][1][1], af[buf][1][2], af[buf][1][3], _a0 + 2048); \
        const uint32_t _b0 = bT + _xb;                                          \
        ldsm4(bf[buf][0][0], bf[buf][0][1], bf[buf][0][2], bf[buf][0][3], _b0); \
        ldsm4(bf[buf][1][0], bf[buf][1][1], bf[buf][1][2], bf[buf][1][3], _b0 + 2048); \
        ldsm4(bf[buf][2][0], bf[buf][2][1], bf[buf][2][2], bf[buf][2][3], _b0 + 4096); \
        ldsm4(bf[buf][3][0], bf[buf][3][1], bf[buf][3][2], bf[buf][3][3], _b0 + 6144); \
    } while (0)

#define K5F_MAINLOOP(gA, gB)                                                    \
    K5F_LOAD(gA, gB, 0, 0); CP_COMMIT();                                        \
    K5F_LOAD(gA, gB, 1, 1); CP_COMMIT();                                        \
    _Pragma("unroll 1")                                                         \
    for (int kc = 0; kc < 6; kc++) {                                            \
        CP_WAIT1();                                                             \
        __syncthreads();                                                        \
        if (kc + 2 < 6) K5F_LOAD(gA, gB, kc + 2, (kc + 2) % K5_STAGES);         \
        CP_COMMIT();                                                            \
        const uint32_t stBase = tb + (kc % K5_STAGES) * K5_STAGE_BYTES;         \
        const uint32_t aT = stBase + aRowOff;                                   \
        const uint32_t bT = stBase + 16384 + bRowOff;                           \
        uint32_t af[2][2][4];                                                   \
        uint32_t bf[2][4][4];                                                   \
        K5F_LDSM(0, 0);                                                         \
        _Pragma("unroll")                                                       \
        for (int ks = 0; ks < 4; ks++) {                                        \
            const int cur = ks & 1;                                             \
            if (ks < 3) { K5F_LDSM((ks + 1) & 1, ks + 1); }                     \
            _Pragma("unroll")                                                   \
            for (int mi = 0; mi < 2; mi++) {                                    \
                _Pragma("unroll")                                               \
                for (int n2 = 0; n2 < 4; n2++) {                                \
                    mma_e4m3(acc[mi][2 * n2], af[cur][mi], bf[cur][n2][0], bf[cur][n2][1]); \
                    mma_e4m3(acc[mi][2 * n2 + 1], af[cur][mi], bf[cur][n2][2], bf[cur][n2][3]); \
                }                                                               \
            }                                                                   \
        }                                                                       \
    }

#define K5F_PROLOG                                                              \
    extern __shared__ char smem[];                                              \
    const uint32_t tb = smem_u32(smem);                                         \
    const int tid = threadIdx.x;                                                \
    const int warp = tid >> 5, lane = tid & 31;                                 \
    const int gid = lane >> 2, tg = lane & 3;                                   \
    const int seg = lane >> 3, l7 = lane & 7;                                   \
    const int arow0 = blockIdx.y * 128;                                         \
    const int brow0 = blockIdx.x * 64;                                          \
    const uint32_t swo0 = (uint32_t)((tid >> 3) * 128 + (((tid & 7) ^ ((tid >> 3) & 7)) * 16)); \
    const uint32_t aRowOff = (uint32_t)((warp * 32 + (seg & 1) * 8 + l7) * 128); \
    const uint32_t bRowOff = (uint32_t)(((seg >> 1) * 8 + l7) * 128);           \
    const uint32_t kselA = (uint32_t)(seg >> 1);                                \
    const uint32_t kselB = (uint32_t)(seg & 1);                                 \
    float acc[2][8][4];                                                         \
    _Pragma("unroll")                                                           \
    for (int mi = 0; mi < 2; mi++)                                              \
        _Pragma("unroll")                                                       \
        for (int ni = 0; ni < 8; ni++)                                          \
            _Pragma("unroll")                                                   \
            for (int rg = 0; rg < 4; rg++) acc[mi][ni][rg] = 0.f;

// ---------------- G1: x @ Wv^T, epilogue relu(acc/64+bv)*cv*2048 -> fp8 ------
__global__ void __launch_bounds__(128, 3) g1_gemm(const float* __restrict__ bias) {
    K5F_PROLOG
    const char* gA = (const char*)g_xf8 + (size_t)(arow0 + (tid >> 3)) * Cc + (tid & 7) * 16;
    const char* gB = (const char*)g_wvf8 + (size_t)(brow0 + (tid >> 3)) * Cc + (tid & 7) * 16;
    K5F_MAINLOOP(gA, gB)

    const float inv64 = 1.f / 64.f;
    const float s2048 = 2048.f;
#pragma unroll
    for (int mi = 0; mi < 2; mi++) {
        int row = arow0 + warp * 32 + mi * 16 + gid;
#pragma unroll
        for (int ni = 0; ni < 8; ni++) {
            int col = brow0 + ni * 8 + tg * 2;
            int hb = (col >> 6) * 129 + 65 + (col & 63);
            float bv0 = bias[hb], bv1 = bias[hb + 1];
            int b = row >> 10;
            float cv0 = g_cv[b * Cc + col], cv1 = g_cv[b * Cc + col + 1];
            float v00 = fmaxf(acc[mi][ni][0] * inv64 + bv0, 0.f) * cv0 * s2048;
            float v01 = fmaxf(acc[mi][ni][1] * inv64 + bv1, 0.f) * cv1 * s2048;
            float v10 = fmaxf(acc[mi][ni][2] * inv64 + bv0, 0.f) * cv0 * s2048;
            float v11 = fmaxf(acc[mi][ni][3] * inv64 + bv1, 0.f) * cv1 * s2048;
            uint16_t* dst = (uint16_t*)g_vf8;
            dst[(size_t)row * (Cc / 2) + col / 2] = f2e4m3x2(v00, v01);
            dst[(size_t)(row + 8) * (Cc / 2) + col / 2] = f2e4m3x2(v10, v11);
        }
    }
}

// ---------------- G2: vf8 @ Wout^T, epilogue acc/(2048*64)+bout -> fp32 -----
__global__ void __launch_bounds__(128, 3) g2_gemm(const float* __restrict__ bias,
                                                  float* __restrict__ outg) {
    K5F_PROLOG
    const char* gA = (const char*)g_vf8 + (size_t)(arow0 + (tid >> 3)) * Cc + (tid & 7) * 16;
    const char* gB = (const char*)g_wof8 + (size_t)(brow0 + (tid >> 3)) * Cc + (tid & 7) * 16;
    K5F_MAINLOOP(gA, gB)

    const float invS = 1.f / (2048.f * 64.f);
#pragma unroll
    for (int mi = 0; mi < 2; mi++) {
        int row = arow0 + warp * 32 + mi * 16 + gid;
#pragma unroll
        for (int ni = 0; ni < 8; ni++) {
            int col = brow0 + ni * 8 + tg * 2;
            float b0 = bias[col], b1 = bias[col + 1];
            *(float2*)(outg + (size_t)row * Cc + col) =
                make_float2(acc[mi][ni][0] * invS + b0, acc[mi][ni][1] * invS + b1);
            *(float2*)(outg + (size_t)(row + 8) * Cc + col) =
                make_float2(acc[mi][ni][2] * invS + b0, acc[mi][ni][3] * invS + b1);
        }
    }
}

// ---------------- launch ----------------------------------------------------
extern "C" void kernel_launch(void* const* d_in, const int* in_sizes, int n_in,
                              void* d_out, int out_size) {
    const float* x = (const float*)d_in[0];
    const float* wqkv = (const float*)d_in[1];
    const float* bqkv = (const float*)d_in[2];
    const float* wcv = (const float*)d_in[3];
    const float* wout = (const float*)d_in[4];
    const float* bout = (const float*)d_in[5];
    float* out = (float*)d_out;

    cudaFuncSetAttribute(k1q_gemm, cudaFuncAttributeMaxDynamicSharedMemorySize, K1Q_SMEM);
    cudaFuncSetAttribute(g1_gemm, cudaFuncAttributeMaxDynamicSharedMemorySize, K5_SMEM);
    cudaFuncSetAttribute(g2_gemm, cudaFuncAttributeMaxDynamicSharedMemorySize, K5_SMEM);

    k1a_conv<<<4096 + Cc, 256>>>(x, wqkv, wout);         // 1
    k1q_gemm<<<512, 128, K1Q_SMEM>>>();                  // 2
    k2_softmax<<<Bb * NHh, 256>>>(wcv);                  // 3
    k3_t<<<dim3(3, Bb, 8), 128>>>();                     // 4
    k4_cv<<<Bb, 256>>>(wqkv, bqkv);                      // 5
    g1_gemm<<<dim3(12, 512), 128, K5_SMEM>>>(bqkv);      // 6
    g2_gemm<<<dim3(12, 512), 128, K5_SMEM>>>(bout, out); // 7
}